// round 1
// baseline (speedup 1.0000x reference)
#include <cuda_runtime.h>

#define T_LEN   750
#define W_LEN   11
#define PAD_LEN (T_LEN + W_LEN)   // 761
#define THREADS 256

// exp(-x/2) = exp2(-x * 0.5 * log2(e))
#define NEG_HALF_LOG2E (-0.7213475204444817f)

__global__ void ae_zero_out(float* out) {
    if (threadIdx.x == 0) out[0] = 0.0f;
}

__global__ __launch_bounds__(THREADS)
void ae_loss_kernel(const float* __restrict__ a0,
                    const float* __restrict__ a2,
                    float* __restrict__ out) {
    __shared__ float s0[PAD_LEN];
    __shared__ float s2[PAD_LEN];
    __shared__ float rw[THREADS / 32];
    __shared__ float rn[THREADS / 32];

    const int b   = blockIdx.x;
    const int tid = threadIdx.x;
    const float* __restrict__ r0 = a0 + (size_t)b * T_LEN;
    const float* __restrict__ r2 = a2 + (size_t)b * T_LEN;

    // Stage padded rows: s[k] = row[clamp(k-6, 0, T-1)]
    for (int k = tid; k < PAD_LEN; k += THREADS) {
        int src = k - 6;
        src = src < 0 ? 0 : (src > T_LEN - 1 ? T_LEN - 1 : src);
        s0[k] = r0[src];
        s2[k] = r2[src];
    }
    __syncthreads();

    float wsum = 0.0f;   // window-weighted |a2 diff| sum
    float nsq  = 0.0f;   // sum of (a0-a2)^2 for the L2 regularizer

    for (int i = tid; i < T_LEN; i += THREADS) {
        const float x0 = s0[i + 6];   // == a0[i]
        const float x2 = s2[i + 6];   // == a2[i]
        const float d  = x0 - x2;
        nsq = fmaf(d, d, nsq);

#pragma unroll
        for (int j = 0; j < W_LEN; j++) {
            const float w0 = s0[i + j];
            const float w2 = s2[i + j];
            const float e  = exp2f(fabsf(x0 - w0) * NEG_HALF_LOG2E);
            wsum = fmaf(e, fabsf(x2 - w2), wsum);
        }
    }

    // Warp reduction
#pragma unroll
    for (int o = 16; o > 0; o >>= 1) {
        wsum += __shfl_down_sync(0xFFFFFFFFu, wsum, o);
        nsq  += __shfl_down_sync(0xFFFFFFFFu, nsq,  o);
    }
    const int warp = tid >> 5, lane = tid & 31;
    if (lane == 0) { rw[warp] = wsum; rn[warp] = nsq; }
    __syncthreads();

    if (warp == 0) {
        constexpr int NW = THREADS / 32;
        wsum = (lane < NW) ? rw[lane] : 0.0f;
        nsq  = (lane < NW) ? rn[lane] : 0.0f;
#pragma unroll
        for (int o = NW / 2; o > 0; o >>= 1) {
            wsum += __shfl_down_sync(0xFFFFFFFFu, wsum, o);
            nsq  += __shfl_down_sync(0xFFFFFFFFu, nsq,  o);
        }
        if (lane == 0) {
            // loss_block = wsum + E_THETA * ||a0 - a2||_2 ; E_ALPHA = 1
            atomicAdd(out, wsum + 0.1f * sqrtf(nsq));
        }
    }
}

extern "C" void kernel_launch(void* const* d_in, const int* in_sizes, int n_in,
                              void* d_out, int out_size) {
    const float* a0 = (const float*)d_in[0];
    const float* a2 = (const float*)d_in[1];
    float* out = (float*)d_out;

    const int B = in_sizes[0] / T_LEN;   // 4096

    ae_zero_out<<<1, 32>>>(out);
    ae_loss_kernel<<<B, THREADS>>>(a0, a2, out);
}

// round 2
// speedup vs baseline: 1.2557x; 1.2557x over previous
#include <cuda_runtime.h>

#define T_LEN   750
#define W_LEN   11
#define CH      4
#define THREADS 192          // 192 * 4 = 768 >= 750
#define PAD2    784          // staged padded length; max idx used = 764+15 = 779

// exp(-x/2) = exp2(-x * 0.5*log2(e))
#define NEG_HALF_LOG2E (-0.7213475204444817f)

__device__ __forceinline__ float ex2_approx(float x) {
    float r;
    asm("ex2.approx.ftz.f32 %0, %1;" : "=f"(r) : "f"(x));
    return r;
}

__global__ void ae_zero_out(float* out) {
    if (threadIdx.x == 0) out[0] = 0.0f;
}

__global__ __launch_bounds__(THREADS)
void ae_loss_kernel(const float* __restrict__ a0,
                    const float* __restrict__ a2,
                    float* __restrict__ out) {
    __shared__ __align__(16) float s0[PAD2];
    __shared__ __align__(16) float s2[PAD2];
    __shared__ float rw[THREADS / 32];
    __shared__ float rn[THREADS / 32];

    const int b   = blockIdx.x;
    const int tid = threadIdx.x;
    const float* __restrict__ g0 = a0 + (size_t)b * T_LEN;
    const float* __restrict__ g2 = a2 + (size_t)b * T_LEN;

    // Stage padded row into shared: s[k] = row[clamp(k-6, 0, T-1)]
    // (k in [0,760] replicates the reference padding; tail up to 783 is
    //  clamped-last so the over-reaching vector loads below read valid data.)
    for (int k = tid; k < PAD2; k += THREADS) {
        int src = k - 6;
        src = src < 0 ? 0 : (src > T_LEN - 1 ? T_LEN - 1 : src);
        s0[k] = g0[src];
        s2[k] = g2[src];
    }
    __syncthreads();

    // Each thread computes CH=4 consecutive outputs i = i_base..i_base+3.
    // All their windows live in padded[i_base .. i_base+13]; grab 16 floats
    // with 4x LDS.128 per array (i_base*4 bytes is 16B-aligned).
    const int i_base = tid * CH;
    float v0[16], v2[16];
    {
        const float4* p0 = reinterpret_cast<const float4*>(s0 + i_base);
        const float4* p2 = reinterpret_cast<const float4*>(s2 + i_base);
#pragma unroll
        for (int q = 0; q < 4; q++) {
            float4 t0 = p0[q];
            float4 t2 = p2[q];
            v0[4*q+0] = t0.x; v0[4*q+1] = t0.y; v0[4*q+2] = t0.z; v0[4*q+3] = t0.w;
            v2[4*q+0] = t2.x; v2[4*q+1] = t2.y; v2[4*q+2] = t2.z; v2[4*q+3] = t2.w;
        }
    }

    float wsum = 0.0f;
    float nsq  = 0.0f;

#pragma unroll
    for (int c = 0; c < CH; c++) {
        if (i_base + c < T_LEN) {
            const float x0 = v0[6 + c];   // == a0[i]
            const float x2 = v2[6 + c];   // == a2[i]
            const float d  = x0 - x2;
            nsq = fmaf(d, d, nsq);

#pragma unroll
            for (int j = 0; j < W_LEN; j++) {
                if (j == 6) continue;     // center term is exp(0)*0 == 0
                const float e = ex2_approx(fabsf(x0 - v0[c + j]) * NEG_HALF_LOG2E);
                wsum = fmaf(e, fabsf(x2 - v2[c + j]), wsum);
            }
        }
    }

    // Warp reduction
#pragma unroll
    for (int o = 16; o > 0; o >>= 1) {
        wsum += __shfl_down_sync(0xFFFFFFFFu, wsum, o);
        nsq  += __shfl_down_sync(0xFFFFFFFFu, nsq,  o);
    }
    const int warp = tid >> 5, lane = tid & 31;
    if (lane == 0) { rw[warp] = wsum; rn[warp] = nsq; }
    __syncthreads();

    if (warp == 0) {
        constexpr int NW = THREADS / 32;   // 6
        wsum = (lane < NW) ? rw[lane] : 0.0f;
        nsq  = (lane < NW) ? rn[lane] : 0.0f;
#pragma unroll
        for (int o = 8; o > 0; o >>= 1) {
            wsum += __shfl_down_sync(0xFFFFFFFFu, wsum, o);
            nsq  += __shfl_down_sync(0xFFFFFFFFu, nsq,  o);
        }
        if (lane == 0) {
            // loss_block = wsum + E_THETA * ||a0 - a2||_2 ; E_ALPHA = 1
            atomicAdd(out, wsum + 0.1f * sqrtf(nsq));
        }
    }
}

extern "C" void kernel_launch(void* const* d_in, const int* in_sizes, int n_in,
                              void* d_out, int out_size) {
    const float* a0 = (const float*)d_in[0];
    const float* a2 = (const float*)d_in[1];
    float* out = (float*)d_out;

    const int B = in_sizes[0] / T_LEN;   // 4096

    ae_zero_out<<<1, 32>>>(out);
    ae_loss_kernel<<<B, THREADS>>>(a0, a2, out);
}